// round 10
// baseline (speedup 1.0000x reference)
#include <cuda_runtime.h>
#include <cuda_bf16.h>
#include <math.h>

// Problem constants
#define B_   4
#define N_   512
#define FIN  64
#define FOUT 128
#define NCH  8           // i-chunks (64 i per chunk) — matches K2 grid.y

// K1 SMEM layout (floats), dynamic
#define XS_OFF   0                    // 16 x 64
#define H0_OFF   1024                 // 16 x 128
#define H1_OFF   3072                 // 16 x 128
#define EW_OFF   5120                 // 128 x 129 (padded)  — reused for W2
#define W0_OFF   21632                // 128 x 65  (padded)
#define W1_OFF   29952                // 128 x 129 (padded)
#define K1_SMEM_FLOATS 46464
#define K1_SMEM_BYTES  (K1_SMEM_FLOATS * 4)

// Scratch (allocation-free rule: __device__ globals)
static __device__ float g_pi   [B_ * N_ * FOUT];          // nodes @ edge_W[:,F:].T
static __device__ float g_pjb  [B_ * N_ * FOUT];          // nodes @ edge_W[:,:F].T + edge_b
static __device__ float g_h    [B_ * N_ * FOUT];          // full MLP output
static __device__ float g_part [B_ * NCH * N_ * FOUT];    // partial sum_i edges (8MB)

__device__ __forceinline__ float celu1(float x) {
    return x > 0.f ? x : expm1f(x);
}

// ---------------------------------------------------------------------------
// K1: 16 rows/block, 256 threads = (f 0..127) x (row-half 0..1), 8 rows each.
// ALL weights staged once into 186KB dynamic SMEM (padded rows -> conflict-
// free scalar weight LDS). 4 barriers total. FMA-pipe bound.
// grid = B*N/16 = 128 blocks.
// ---------------------------------------------------------------------------
__global__ __launch_bounds__(256) void k1_pernode(
    const float* __restrict__ nodes,
    const float* __restrict__ eW, const float* __restrict__ eb,
    const float* __restrict__ W0, const float* __restrict__ b0,
    const float* __restrict__ W1, const float* __restrict__ b1,
    const float* __restrict__ W2, const float* __restrict__ b2)
{
    extern __shared__ float smem[];
    float* xs  = smem + XS_OFF;
    float* h0s = smem + H0_OFF;
    float* h1s = smem + H1_OFF;
    float* sew = smem + EW_OFF;   // eW padded 129; later W2
    float* sw0 = smem + W0_OFF;   // W0 padded 65
    float* sw1 = smem + W1_OFF;   // W1 padded 129

    const int row0  = blockIdx.x * 16;
    const int tid   = threadIdx.x;
    const int f     = tid & 127;
    const int rbase = (tid >> 7) * 8;    // rows rbase..rbase+7 of the 16

    // --- load activations (16 rows x 64 = 256 float4, one per thread) ---
    {
        float4*       x4 = (float4*)xs;
        const float4* gx = (const float4*)(nodes + (size_t)row0 * FIN);
        x4[tid] = gx[tid];
    }
    // --- stage eW [128x128 -> pad 129], W0 [128x64 -> pad 65], W1 [pad 129] ---
    #pragma unroll 4
    for (int t = tid; t < 128 * 128; t += 256) {
        int fr = t >> 7, k = t & 127;
        sew[fr * 129 + k] = eW[t];
    }
    #pragma unroll 4
    for (int t = tid; t < 128 * 64; t += 256) {
        int fr = t >> 6, k = t & 63;
        sw0[fr * 65 + k] = W0[t];
    }
    #pragma unroll 4
    for (int t = tid; t < 128 * 128; t += 256) {
        int fr = t >> 7, k = t & 127;
        sw1[fr * 129 + k] = W1[t];
    }
    __syncthreads();

    const float4* x4  = (const float4*)xs;
    const float4* h04 = (const float4*)h0s;
    const float4* h14 = (const float4*)h1s;

    // --- eW phase: pj (k 0..63) and pi (k 64..127) for 8 rows ---
    {
        const float* wrow = sew + f * 129;
        float accj[8], acci[8];
        #pragma unroll
        for (int r = 0; r < 8; r++) { accj[r] = 0.f; acci[r] = 0.f; }
        #pragma unroll
        for (int k4 = 0; k4 < 16; k4++) {
            float wj0 = wrow[4*k4+0], wj1 = wrow[4*k4+1];
            float wj2 = wrow[4*k4+2], wj3 = wrow[4*k4+3];
            float wi0 = wrow[64+4*k4+0], wi1 = wrow[64+4*k4+1];
            float wi2 = wrow[64+4*k4+2], wi3 = wrow[64+4*k4+3];
            #pragma unroll
            for (int r = 0; r < 8; r++) {
                float4 v = x4[(rbase + r) * 16 + k4];
                accj[r] += wj0*v.x + wj1*v.y + wj2*v.z + wj3*v.w;
                acci[r] += wi0*v.x + wi1*v.y + wi2*v.z + wi3*v.w;
            }
        }
        const float ebf = eb[f];
        #pragma unroll
        for (int r = 0; r < 8; r++) {
            g_pjb[(size_t)(row0 + rbase + r) * FOUT + f] = accj[r] + ebf;
            g_pi [(size_t)(row0 + rbase + r) * FOUT + f] = acci[r];
        }
    }

    // --- MLP layer 0 (K=64) + CELU -> h0s ---
    {
        const float* wrow = sw0 + f * 65;
        const float  bf = b0[f];
        float acc[8];
        #pragma unroll
        for (int r = 0; r < 8; r++) acc[r] = bf;
        #pragma unroll
        for (int k4 = 0; k4 < 16; k4++) {
            float w0v = wrow[4*k4+0], w1v = wrow[4*k4+1];
            float w2v = wrow[4*k4+2], w3v = wrow[4*k4+3];
            #pragma unroll
            for (int r = 0; r < 8; r++) {
                float4 v = x4[(rbase + r) * 16 + k4];
                acc[r] += w0v*v.x + w1v*v.y + w2v*v.z + w3v*v.w;
            }
        }
        #pragma unroll
        for (int r = 0; r < 8; r++)
            h0s[(rbase + r) * FOUT + f] = celu1(acc[r]);
    }
    __syncthreads();

    // --- MLP layer 1 (K=128) + CELU -> h1s ---
    {
        const float* wrow = sw1 + f * 129;
        const float  bf = b1[f];
        float acc[8];
        #pragma unroll
        for (int r = 0; r < 8; r++) acc[r] = bf;
        #pragma unroll
        for (int k4 = 0; k4 < 32; k4++) {
            float w0v = wrow[4*k4+0], w1v = wrow[4*k4+1];
            float w2v = wrow[4*k4+2], w3v = wrow[4*k4+3];
            #pragma unroll
            for (int r = 0; r < 8; r++) {
                float4 v = h04[(rbase + r) * 32 + k4];
                acc[r] += w0v*v.x + w1v*v.y + w2v*v.z + w3v*v.w;
            }
        }
        #pragma unroll
        for (int r = 0; r < 8; r++)
            h1s[(rbase + r) * FOUT + f] = celu1(acc[r]);
    }
    __syncthreads();   // h1s ready AND all reads of sew (eW phase) long done

    // --- stage W2 into the eW slot ---
    #pragma unroll 4
    for (int t = tid; t < 128 * 128; t += 256) {
        int fr = t >> 7, k = t & 127;
        sew[fr * 129 + k] = W2[t];
    }
    __syncthreads();

    // --- MLP layer 2 (K=128) -> g_h ---
    {
        const float* wrow = sew + f * 129;
        const float  bf = b2[f];
        float acc[8];
        #pragma unroll
        for (int r = 0; r < 8; r++) acc[r] = bf;
        #pragma unroll
        for (int k4 = 0; k4 < 32; k4++) {
            float w0v = wrow[4*k4+0], w1v = wrow[4*k4+1];
            float w2v = wrow[4*k4+2], w3v = wrow[4*k4+3];
            #pragma unroll
            for (int r = 0; r < 8; r++) {
                float4 v = h14[(rbase + r) * 32 + k4];
                acc[r] += w0v*v.x + w1v*v.y + w2v*v.z + w3v*v.w;
            }
        }
        #pragma unroll
        for (int r = 0; r < 8; r++)
            g_h[(size_t)(row0 + rbase + r) * FOUT + f] = acc[r];
    }
}

// ---------------------------------------------------------------------------
// K2: edges writer WITH fused i-partial reduction. (unchanged from R8 pass)
// Tile: 64 (i) x 16 (j) per block. grid = (N/16, N/64, B) = 32x8x4, 256 thr.
// ---------------------------------------------------------------------------
__global__ __launch_bounds__(256) void k2_edges(
    const float* __restrict__ sk, float* __restrict__ edges)
{
    const int b  = blockIdx.z;
    const int iy = blockIdx.y;           // i-chunk 0..7
    const int i0 = iy * 64;
    const int j0 = blockIdx.x * 16;
    const int tid = threadIdx.x;

    __shared__ float4 spi [64][32];      // 32KB
    __shared__ float4 spjb[16][32];      // 8KB
    __shared__ float  ssk [64][16];      // 4KB

    const float4* gpi  = (const float4*)(g_pi  + ((size_t)(b * N_ + i0)) * FOUT);
    const float4* gpjb = (const float4*)(g_pjb + ((size_t)(b * N_ + j0)) * FOUT);
    #pragma unroll
    for (int t = tid; t < 2048; t += 256)
        spi[t >> 5][t & 31] = gpi[t];
    #pragma unroll
    for (int t = tid; t < 512; t += 256)
        spjb[t >> 5][t & 31] = gpjb[t];
    #pragma unroll
    for (int t = tid; t < 1024; t += 256) {
        int ii = t >> 4, jj = t & 15;
        ssk[ii][jj] = sk[((size_t)(b * N_ + i0 + ii)) * N_ + j0 + jj];
    }
    __syncthreads();

    const int lane = tid & 31;
    const int w    = tid >> 5;           // warp 0..7 -> jj in {w, w+8}

    const float4 c0 = spjb[w][lane];
    const float4 c1 = spjb[w + 8][lane];

    float4 acc0 = make_float4(0.f, 0.f, 0.f, 0.f);
    float4 acc1 = make_float4(0.f, 0.f, 0.f, 0.f);

    float4* __restrict__ e4 = (float4*)edges;
    const size_t base = ((size_t)(b * N_ + i0) * N_ + j0) * 32 + lane;

    #pragma unroll 4
    for (int ii = 0; ii < 64; ii++) {
        float4 a  = spi[ii][lane];
        float  s0 = ssk[ii][w];
        float  s1 = ssk[ii][w + 8];
        float4 e0, e1;
        e0.x = (a.x + c0.x) * s0;  e0.y = (a.y + c0.y) * s0;
        e0.z = (a.z + c0.z) * s0;  e0.w = (a.w + c0.w) * s0;
        e1.x = (a.x + c1.x) * s1;  e1.y = (a.y + c1.y) * s1;
        e1.z = (a.z + c1.z) * s1;  e1.w = (a.w + c1.w) * s1;
        size_t rbase = base + (size_t)ii * (N_ * 32);
        __stcs(&e4[rbase + (size_t)w * 32],        e0);
        __stcs(&e4[rbase + (size_t)(w + 8) * 32],  e1);
        acc0.x += e0.x; acc0.y += e0.y; acc0.z += e0.z; acc0.w += e0.w;
        acc1.x += e1.x; acc1.y += e1.y; acc1.z += e1.z; acc1.w += e1.w;
    }

    // write partials: g_part[b][iy][j][f]  (FULL edge sums — nothing added later)
    float4* p4 = (float4*)g_part;
    size_t pbase = (((size_t)(b * NCH + iy) * N_) + j0) * 32 + lane;
    p4[pbase + (size_t)w * 32]       = acc0;
    p4[pbase + (size_t)(w + 8) * 32] = acc1;
}

// ---------------------------------------------------------------------------
// K3: fold partials (already complete edge sums), node_W GEMV + bias + h.
// 2 j-rows per block. grid = (N/2, B) = 1024 blocks, 128 threads (f).
// ---------------------------------------------------------------------------
__global__ __launch_bounds__(128) void k3_final(
    const float* __restrict__ nW, const float* __restrict__ nb,
    float* __restrict__ out1)
{
    const int b  = blockIdx.y;
    const int j0 = blockIdx.x * 2;
    const int f  = threadIdx.x;

    __shared__ float nn[2][FOUT];

    float acc0 = 0.f, acc1 = 0.f;
    #pragma unroll
    for (int c = 0; c < NCH; c++) {
        const float* pr = g_part + (((size_t)(b * NCH + c) * N_) + j0) * FOUT + f;
        acc0 += pr[0];
        acc1 += pr[FOUT];
    }
    nn[0][f] = acc0;
    nn[1][f] = acc1;
    __syncthreads();

    const float nbf = nb[f];
    float o0 = nbf, o1 = nbf;
    const float4* nwr = (const float4*)(nW + (size_t)f * FOUT);
    #pragma unroll 8
    for (int k = 0; k < 32; k++) {
        float4 w  = nwr[k];
        float4 n0 = ((const float4*)nn[0])[k];
        float4 n1 = ((const float4*)nn[1])[k];
        o0 += w.x*n0.x + w.y*n0.y + w.z*n0.z + w.w*n0.w;
        o1 += w.x*n1.x + w.y*n1.y + w.z*n1.z + w.w*n1.w;
    }

    const float* hr = g_h + ((size_t)(b * N_ + j0)) * FOUT;
    out1[((size_t)(b * N_ + j0))     * FOUT + f] = o0 + hr[f];
    out1[((size_t)(b * N_ + j0 + 1)) * FOUT + f] = o1 + hr[FOUT + f];
}

// ---------------------------------------------------------------------------
extern "C" void kernel_launch(void* const* d_in, const int* in_sizes, int n_in,
                              void* d_out, int out_size)
{
    const float* nodes = (const float*)d_in[0];
    const float* sk    = (const float*)d_in[1];
    const float* eW    = (const float*)d_in[2];
    const float* eb    = (const float*)d_in[3];
    const float* nW    = (const float*)d_in[4];
    const float* nb    = (const float*)d_in[5];
    const float* W0    = (const float*)d_in[6];
    const float* b0    = (const float*)d_in[7];
    const float* W1    = (const float*)d_in[8];
    const float* b1    = (const float*)d_in[9];
    const float* W2    = (const float*)d_in[10];
    const float* b2    = (const float*)d_in[11];

    float* out1  = (float*)d_out;                            // [B,N,F_OUT]
    float* edges = (float*)d_out + (size_t)B_ * N_ * FOUT;   // [B,N,N,F_OUT]

    // allow 186KB dynamic SMEM for k1 (idempotent; immediate, not captured)
    cudaFuncSetAttribute(k1_pernode,
                         cudaFuncAttributeMaxDynamicSharedMemorySize,
                         K1_SMEM_BYTES);

    k1_pernode<<<(B_ * N_) / 16, 256, K1_SMEM_BYTES>>>(
        nodes, eW, eb, W0, b0, W1, b1, W2, b2);

    dim3 g2(N_ / 16, N_ / 64, B_);
    k2_edges<<<g2, 256>>>(sk, edges);

    dim3 g3(N_ / 2, B_);
    k3_final<<<g3, 128>>>(nW, nb, out1);
}